// round 6
// baseline (speedup 1.0000x reference)
#include <cuda_runtime.h>
#include <math.h>

// ---------------------------------------------------------------------------
// Problem constants
// ---------------------------------------------------------------------------
#define BB    4
#define CINF  320
#define DD    33
#define KK    5
#define D2C   1089          // 33*33
#define D3C   35937         // 33^3
#define NJC   539055        // 3*D^3*K
#define LUTBK 107811        // 3*D^3  (stride per (b,k))
#define HWC   65536         // 256*256
#define NPIXC 262144        // B*H*W
#define NOISE_N 16384       // 4*4*32*32
#define OUT_LUT_OFF 16384
#define OUT_LOSS_OFF 802816
#define NREG  2156220       // B*K*3*D^3

// ---------------------------------------------------------------------------
// Scratch (static device globals: no allocation allowed)
// ---------------------------------------------------------------------------
__device__ float g_pooled[BB * 256];
__device__ float g_lut[BB * NJC];              // [B, K,3,D,D,D]
__device__ float g_r0 [BB * KK * 1024];        // raw (pre-relu) routing conv0
__device__ float g_r1 [BB * KK * 1024];
__device__ float g_rt0[BB * KK * 4096];
__device__ float g_r2 [BB * KK * 4096];
__device__ float g_rt1[BB * KK * 16384];
__device__ float g_r3 [BB * KK * 16384];
__device__ float g_rt2[BB * KK * 65536];
__device__ float g_acc[4];                     // tv, mn, wnorm

// ---------------------------------------------------------------------------
// Packed fp32x2 FMA (sm_100+): 2 fp32 FMAs per issue slot
// ---------------------------------------------------------------------------
__device__ __forceinline__ float2 ffma2(float2 a, float2 w, float2 c) {
    float2 d;
    asm("{\n\t"
        ".reg .b64 ra, rb, rc, rd;\n\t"
        "mov.b64 ra, {%2, %3};\n\t"
        "mov.b64 rb, {%4, %5};\n\t"
        "mov.b64 rc, {%6, %7};\n\t"
        "fma.rn.f32x2 rd, ra, rb, rc;\n\t"
        "mov.b64 {%0, %1}, rd;\n\t"
        "}"
        : "=f"(d.x), "=f"(d.y)
        : "f"(a.x), "f"(a.y), "f"(w.x), "f"(w.y), "f"(c.x), "f"(c.y));
    return d;
}

// ---------------------------------------------------------------------------
// K0: zero noise region of out + routing raw buffer + accumulators
// ---------------------------------------------------------------------------
__global__ void k_init(float* __restrict__ out) {
    int i = blockIdx.x * 256 + threadIdx.x;
    if (i < NOISE_N) out[i] = 0.f;
    if (i < BB * KK * 1024) g_r0[i] = 0.f;
    if (i < 4) g_acc[i] = 0.f;
}

// ---------------------------------------------------------------------------
// K1: noise_pred conv3x3 320->4 @32x32, split over cin groups (atomic adds)
// grid: (16 = b*4+co, 8 = cin group of 40), block 256
// ---------------------------------------------------------------------------
__global__ void k_noise(const float* __restrict__ feat, const float* __restrict__ w,
                        const float* __restrict__ bias, float* __restrict__ out) {
    __shared__ float plane[1024];
    __shared__ float ws[9];
    const int bx = blockIdx.x;
    const int b = bx >> 2, co = bx & 3;
    const int g = blockIdx.y;
    const int t = threadIdx.x;
    const int row = t >> 3, col = (t & 7) << 2;
    float bv = (g == 0) ? bias[co] : 0.f;
    float a0 = bv, a1 = bv, a2 = bv, a3 = bv;
    for (int ci = 0; ci < 40; ++ci) {
        const int cin = g * 40 + ci;
        reinterpret_cast<float4*>(plane)[t] =
            reinterpret_cast<const float4*>(feat + ((size_t)(b * CINF + cin) << 10))[t];
        if (t < 9) ws[t] = w[(co * CINF + cin) * 9 + t];
        __syncthreads();
#pragma unroll
        for (int ky = 0; ky < 3; ++ky) {
            const int r = row + ky - 1;
            if ((unsigned)r < 32u) {
                float v[6];
#pragma unroll
                for (int i = 0; i < 6; ++i) {
                    int c = col + i - 1;
                    v[i] = ((unsigned)c < 32u) ? plane[(r << 5) + c] : 0.f;
                }
#pragma unroll
                for (int kx = 0; kx < 3; ++kx) {
                    const float wv = ws[ky * 3 + kx];
                    a0 += wv * v[kx];     a1 += wv * v[kx + 1];
                    a2 += wv * v[kx + 2]; a3 += wv * v[kx + 3];
                }
            }
        }
        __syncthreads();
    }
    float* o = out + ((b * 4 + co) << 10) + (row << 5) + col;
    atomicAdd(o + 0, a0); atomicAdd(o + 1, a1);
    atomicAdd(o + 2, a2); atomicAdd(o + 3, a3);
}

// ---------------------------------------------------------------------------
// K2: lut-branch conv3x3 320->256 + bias + relu + global avg pool -> pooled
// f32x2 packed FMA version: thread = 8 consecutive px x 4 couts.
// Block 256 threads: half 0 (t<128) -> couts co0..co0+3, half 1 -> co0+4..co0+7.
// grid: (32 cout-groups of 8, 4 b)
// ---------------------------------------------------------------------------
__global__ void k_lbconv(const float* __restrict__ feat, const float* __restrict__ w1,
                         const float* __restrict__ b1) {
    __shared__ __align__(16) float plane[1024];
    __shared__ float2 ws2[72];                 // 8 couts x 9 taps, duplicated (w,w)
    __shared__ float wred[8][4];
    const int b = blockIdx.y;
    const int co0 = blockIdx.x << 3;
    const int t = threadIdx.x;
    const int half = t >> 7;
    const int tt = t & 127;
    const int row = tt >> 2;
    const int col0 = (tt & 3) << 3;            // 0,8,16,24

    float2 acc[4][4];
#pragma unroll
    for (int co = 0; co < 4; ++co)
#pragma unroll
        for (int q = 0; q < 4; ++q) acc[co][q] = make_float2(0.f, 0.f);

    for (int cin = 0; cin < CINF; ++cin) {
        reinterpret_cast<float4*>(plane)[t] =
            reinterpret_cast<const float4*>(feat + ((size_t)(b * CINF + cin) << 10))[t];
        if (t < 72) {
            const float wv = w1[((co0 + t / 9) * CINF + cin) * 9 + (t % 9)];
            ws2[t] = make_float2(wv, wv);
        }
        __syncthreads();
#pragma unroll
        for (int ky = 0; ky < 3; ++ky) {
            const int rr = row + ky - 1;
            if ((unsigned)rr < 32u) {
                const float* rp = plane + (rr << 5) + col0;
                float2 E[4];
#pragma unroll
                for (int i = 0; i < 4; ++i)
                    E[i] = *reinterpret_cast<const float2*>(rp + (i << 1));
                const float vm1 = (col0 > 0)  ? rp[-1] : 0.f;
                const float v8  = (col0 < 24) ? rp[8]  : 0.f;
                float2 O[5];
                O[0] = make_float2(vm1,    E[0].x);
                O[1] = make_float2(E[0].y, E[1].x);
                O[2] = make_float2(E[1].y, E[2].x);
                O[3] = make_float2(E[2].y, E[3].x);
                O[4] = make_float2(E[3].y, v8);
#pragma unroll
                for (int co = 0; co < 4; ++co) {
                    const int wb = ((half << 2) + co) * 9 + ky * 3;
                    const float2 w0 = ws2[wb + 0];
                    const float2 w1v = ws2[wb + 1];
                    const float2 w2 = ws2[wb + 2];
#pragma unroll
                    for (int q = 0; q < 4; ++q) {
                        acc[co][q] = ffma2(O[q],     w0,  acc[co][q]);
                        acc[co][q] = ffma2(E[q],     w1v, acc[co][q]);
                        acc[co][q] = ffma2(O[q + 1], w2,  acc[co][q]);
                    }
                }
            }
        }
        __syncthreads();
    }

    // relu + pool
    const int lane = t & 31, wp = t >> 5;
#pragma unroll
    for (int co = 0; co < 4; ++co) {
        const float bv = b1[co0 + (half << 2) + co];
        float s = 0.f;
#pragma unroll
        for (int q = 0; q < 4; ++q)
            s += fmaxf(acc[co][q].x + bv, 0.f) + fmaxf(acc[co][q].y + bv, 0.f);
#pragma unroll
        for (int o = 16; o > 0; o >>= 1) s += __shfl_xor_sync(0xffffffffu, s, o);
        if (lane == 0) wred[wp][co] = s;
    }
    __syncthreads();
    if (t < 8) {
        // co_global = t; half = t>>2 -> warps [half*4, half*4+4)
        float s = 0.f;
#pragma unroll
        for (int i = 0; i < 4; ++i) s += wred[((t >> 2) << 2) + i][t & 3];
        g_pooled[b * 256 + co0 + t] = s * (1.f / 1024.f);
    }
}

// ---------------------------------------------------------------------------
// K3: lut_params[b,j] = pooled[b,:] . w2[j,:] + b2[j]   (DRAM-bound: 552 MB)
// ---------------------------------------------------------------------------
__global__ void k_gemm(const float* __restrict__ w2, const float* __restrict__ b2) {
    __shared__ __align__(16) float sp[1024];
    const int t = threadIdx.x;
#pragma unroll
    for (int i = 0; i < 4; ++i) sp[t + (i << 8)] = g_pooled[t + (i << 8)];
    __syncthreads();
    const int jb = (blockIdx.x << 10) + t;
    float acc[4][4];
#pragma unroll
    for (int i = 0; i < 4; ++i)
#pragma unroll
        for (int q = 0; q < 4; ++q) acc[i][q] = 0.f;
    const float4* w2v = reinterpret_cast<const float4*>(w2);
#pragma unroll 2
    for (int c4 = 0; c4 < 64; ++c4) {
        const float4 p0 = *reinterpret_cast<const float4*>(sp + (c4 << 2));
        const float4 p1 = *reinterpret_cast<const float4*>(sp + 256 + (c4 << 2));
        const float4 p2 = *reinterpret_cast<const float4*>(sp + 512 + (c4 << 2));
        const float4 p3 = *reinterpret_cast<const float4*>(sp + 768 + (c4 << 2));
#pragma unroll
        for (int i = 0; i < 4; ++i) {
            const int j = jb + (i << 8);
            if (j < NJC) {
                const float4 wv = __ldg(w2v + (size_t)j * 64 + c4);
                acc[i][0] += wv.x * p0.x + wv.y * p0.y + wv.z * p0.z + wv.w * p0.w;
                acc[i][1] += wv.x * p1.x + wv.y * p1.y + wv.z * p1.z + wv.w * p1.w;
                acc[i][2] += wv.x * p2.x + wv.y * p2.y + wv.z * p2.z + wv.w * p2.w;
                acc[i][3] += wv.x * p3.x + wv.y * p3.y + wv.z * p3.z + wv.w * p3.w;
            }
        }
    }
#pragma unroll
    for (int i = 0; i < 4; ++i) {
        const int j = jb + (i << 8);
        if (j < NJC) {
            const float bv = b2[j];
#pragma unroll
            for (int q = 0; q < 4; ++q) g_lut[(size_t)q * NJC + j] = acc[i][q] + bv;
        }
    }
}

// ---------------------------------------------------------------------------
// Routing network. conv0: thread = 1 pixel, all 5 experts; cin split into
// 4 groups of 80 (atomics into g_r0, relu deferred to the next conv's load).
// grid: (32, 4 cin-groups), block 128
// ---------------------------------------------------------------------------
__global__ void k_route0(const float* __restrict__ feat, const float* __restrict__ w0,
                         const float* __restrict__ b0) {
    const int t = threadIdx.x;
    const int gp = blockIdx.x * 128 + t;   // 0..4095 = b*1024 + p
    const int b = gp >> 10, p = gp & 1023;
    const int c0 = blockIdx.y * 80;
    float acc[KK];
#pragma unroll
    for (int k = 0; k < KK; ++k) acc[k] = 0.f;
    const float* f = feat + ((size_t)(b * CINF + c0) << 10) + p;
#pragma unroll 8
    for (int c = 0; c < 80; ++c) {
        const float v = f[(size_t)c << 10];
#pragma unroll
        for (int k = 0; k < KK; ++k) acc[k] += v * __ldg(w0 + k * CINF + c0 + c);
    }
    if (blockIdx.y == 0) {
#pragma unroll
        for (int k = 0; k < KK; ++k) acc[k] += b0[k];
    }
#pragma unroll
    for (int k = 0; k < KK; ++k)
        atomicAdd(&g_r0[((b * KK + k) << 10) + p], acc[k]);
}

template <int S, bool RELU_IN>
__device__ __forceinline__ void conv3_impl(const float* __restrict__ in,
                                           const float* __restrict__ w,
                                           const float* __restrict__ bias,
                                           float* __restrict__ outp) {
    const int idx = blockIdx.x * 256 + threadIdx.x;
    if (idx >= BB * KK * S * S) return;
    const int x = idx % S;
    const int y = (idx / S) % S;
    const int k = (idx / (S * S)) % KK;
    const int b = idx / (S * S * KK);
    float acc = bias[k];
#pragma unroll
    for (int c = 0; c < KK; ++c) {
        const float* ip = in + (size_t)(b * KK + c) * S * S;
        const float* wp = w + (k * KK + c) * 9;
#pragma unroll
        for (int ky = 0; ky < 3; ++ky) {
            const int yy = y + ky - 1;
            if ((unsigned)yy < (unsigned)S) {
#pragma unroll
                for (int kx = 0; kx < 3; ++kx) {
                    const int xx = x + kx - 1;
                    if ((unsigned)xx < (unsigned)S) {
                        float v = ip[yy * S + xx];
                        if (RELU_IN) v = fmaxf(v, 0.f);
                        acc += v * __ldg(wp + ky * 3 + kx);
                    }
                }
            }
        }
    }
    outp[idx] = fmaxf(acc, 0.f);
}

template <int Sin>
__device__ __forceinline__ void convT_impl(const float* __restrict__ in,
                                           const float* __restrict__ w,
                                           const float* __restrict__ bias,
                                           float* __restrict__ outp) {
    constexpr int So = 2 * Sin;
    const int idx = blockIdx.x * 256 + threadIdx.x;
    if (idx >= BB * KK * So * So) return;
    const int ox = idx % So;
    const int oy = (idx / So) % So;
    const int k = (idx / (So * So)) % KK;
    const int b = idx / (So * So * KK);
    float acc = bias[k];
    const int py = (oy + 1) & 1, px = (ox + 1) & 1;
#pragma unroll
    for (int c = 0; c < KK; ++c) {
        const float* ip = in + (size_t)(b * KK + c) * Sin * Sin;
        const float* wp = w + (c * KK + k) * 16;
#pragma unroll
        for (int jy = 0; jy < 2; ++jy) {
            const int ky = py + 2 * jy;
            const int ny = oy + 1 - ky;
            const int iy = ny >> 1;
            if (ny >= 0 && iy < Sin) {
#pragma unroll
                for (int jx = 0; jx < 2; ++jx) {
                    const int kx = px + 2 * jx;
                    const int nx = ox + 1 - kx;
                    const int ix = nx >> 1;
                    if (nx >= 0 && ix < Sin)
                        acc += ip[iy * Sin + ix] * __ldg(wp + ky * 4 + kx);
                }
            }
        }
    }
    outp[idx] = acc;
}

__global__ void k_conv3_32 (const float* w, const float* b) { conv3_impl<32, true> (g_r0,  w, b, g_r1 ); }
__global__ void k_convt_32 (const float* w, const float* b) { convT_impl<32> (g_r1,  w, b, g_rt0); }
__global__ void k_conv3_64 (const float* w, const float* b) { conv3_impl<64, false>(g_rt0, w, b, g_r2 ); }
__global__ void k_convt_64 (const float* w, const float* b) { convT_impl<64> (g_r2,  w, b, g_rt1); }
__global__ void k_conv3_128(const float* w, const float* b) { conv3_impl<128, false>(g_rt1, w, b, g_r3 ); }
__global__ void k_convt_128(const float* w, const float* b) { convT_impl<128>(g_r3,  w, b, g_rt2); }

// ---------------------------------------------------------------------------
// K5: TV + monotonicity regularizers over g_lut (single pass, fused dirs)
// ---------------------------------------------------------------------------
__global__ void k_reg() {
    const int idx = blockIdx.x * 256 + threadIdx.x;
    float tv = 0.f, mn = 0.f;
    if (idx < NREG) {
        const int x = idx % 33;
        const int r1 = idx / 33;
        const int y = r1 % 33;
        const int z = (r1 / 33) % 33;
        const float v = g_lut[idx];
        if (x < 32) {
            const float d = v - g_lut[idx + 1];
            const float w = (x == 0 || x == 31) ? 2.f : 1.f;
            tv += d * d * w; mn += fmaxf(d, 0.f);
        }
        if (y < 32) {
            const float d = v - g_lut[idx + 33];
            const float w = (y == 0 || y == 31) ? 2.f : 1.f;
            tv += d * d * w; mn += fmaxf(d, 0.f);
        }
        if (z < 32) {
            const float d = v - g_lut[idx + 1089];
            const float w = (z == 0 || z == 31) ? 2.f : 1.f;
            tv += d * d * w; mn += fmaxf(d, 0.f);
        }
    }
#pragma unroll
    for (int o = 16; o > 0; o >>= 1) {
        tv += __shfl_xor_sync(0xffffffffu, tv, o);
        mn += __shfl_xor_sync(0xffffffffu, mn, o);
    }
    __shared__ float stv[8], smn[8];
    const int lane = threadIdx.x & 31, wp = threadIdx.x >> 5;
    if (lane == 0) { stv[wp] = tv; smn[wp] = mn; }
    __syncthreads();
    if (threadIdx.x == 0) {
        float a = 0.f, m = 0.f;
#pragma unroll
        for (int i = 0; i < 8; ++i) { a += stv[i]; m += smn[i]; }
        atomicAdd(&g_acc[0], a);
        atomicAdd(&g_acc[1], m);
    }
}

// ---------------------------------------------------------------------------
// K6: softmax routing + trilinear LUT blend + weights_norm  (1 thread/pixel)
// ---------------------------------------------------------------------------
__global__ void k_final(const float* __restrict__ img, float* __restrict__ out) {
    const int pix = blockIdx.x * 256 + threadIdx.x;  // exactly NPIXC threads
    const int b = pix >> 16;
    const int p = pix & 0xFFFF;

    const float rn = img[(size_t)(b * 3 + 0) * HWC + p] * 0.5f + 0.5f;
    const float gn = img[(size_t)(b * 3 + 1) * HWC + p] * 0.5f + 0.5f;
    const float bn = img[(size_t)(b * 3 + 2) * HWC + p] * 0.5f + 0.5f;
    const float cx = fminf(fmaxf(rn * 32.f, 0.f), 32.f);
    const float cy = fminf(fmaxf(gn * 32.f, 0.f), 32.f);
    const float cz = fminf(fmaxf(bn * 32.f, 0.f), 32.f);
    const int x0 = min((int)cx, 31);
    const int y0 = min((int)cy, 31);
    const int z0 = min((int)cz, 31);
    const float xd = cx - (float)x0, yd = cy - (float)y0, zd = cz - (float)z0;

    float rv[5];
    const float* rf = g_rt2 + (size_t)(b * KK) * HWC + p;
    float m = -1e30f;
#pragma unroll
    for (int k = 0; k < KK; ++k) { rv[k] = rf[(size_t)k * HWC]; m = fmaxf(m, rv[k]); }
    float se = 0.f;
#pragma unroll
    for (int k = 0; k < KK; ++k) { rv[k] = expf(rv[k] - m); se += rv[k]; }
    const float inv = 1.f / se;

    const int o000 = z0 * D2C + y0 * 33 + x0;
    float a0 = 0.f, a1 = 0.f, a2 = 0.f, wn = 0.f;
#pragma unroll
    for (int k = 0; k < KK; ++k) {
        const float pw = rv[k] * inv;
        wn += pw * pw;
        const float* L = g_lut + (size_t)(b * KK + k) * LUTBK + o000;
#pragma unroll
        for (int ch = 0; ch < 3; ++ch) {
            const float* Lc = L + ch * D3C;
            const float c000 = Lc[0],    c001 = Lc[1];
            const float c010 = Lc[33],   c011 = Lc[34];
            const float c100 = Lc[1089], c101 = Lc[1090];
            const float c110 = Lc[1122], c111 = Lc[1123];
            const float c00 = c000 + (c001 - c000) * xd;
            const float c01 = c010 + (c011 - c010) * xd;
            const float c10 = c100 + (c101 - c100) * xd;
            const float c11 = c110 + (c111 - c110) * xd;
            const float c0 = c00 + (c01 - c00) * yd;
            const float c1 = c10 + (c11 - c10) * yd;
            const float val = c0 + (c1 - c0) * zd;
            if (ch == 0) a0 += val * pw;
            else if (ch == 1) a1 += val * pw;
            else a2 += val * pw;
        }
    }
    out[OUT_LUT_OFF + (size_t)(b * 3 + 0) * HWC + p] = a0;
    out[OUT_LUT_OFF + (size_t)(b * 3 + 1) * HWC + p] = a1;
    out[OUT_LUT_OFF + (size_t)(b * 3 + 2) * HWC + p] = a2;

#pragma unroll
    for (int o = 16; o > 0; o >>= 1) wn += __shfl_xor_sync(0xffffffffu, wn, o);
    __shared__ float swn[8];
    const int lane = threadIdx.x & 31, wp = threadIdx.x >> 5;
    if (lane == 0) swn[wp] = wn;
    __syncthreads();
    if (threadIdx.x == 0) {
        float s = 0.f;
#pragma unroll
        for (int i = 0; i < 8; ++i) s += swn[i];
        atomicAdd(&g_acc[2], s);
    }
}

// ---------------------------------------------------------------------------
// K7: combine regularizers into reg_loss
// ---------------------------------------------------------------------------
__global__ void k_loss(float* __restrict__ out) {
    const float tv = g_acc[0] * (1.f / 104544.f);   // 3*33*33*32
    const float mn = g_acc[1] * (1.f / 104544.f);
    const float wn = g_acc[2] * (1.f / 1310720.f);  // 4*5*256*256
    out[OUT_LOSS_OFF] = 0.0005f * (wn + tv * 0.25f) + 10.f * (mn * 0.25f);
}

// ---------------------------------------------------------------------------
extern "C" void kernel_launch(void* const* d_in, const int* in_sizes, int n_in,
                              void* d_out, int out_size) {
    const float* feat = (const float*)d_in[0];
    const float* img  = (const float*)d_in[1];
    const float* cw   = (const float*)d_in[2];
    const float* cb   = (const float*)d_in[3];
    const float* w1   = (const float*)d_in[4];
    const float* b1   = (const float*)d_in[5];
    const float* w2   = (const float*)d_in[6];
    const float* b2   = (const float*)d_in[7];
    const float* rw0  = (const float*)d_in[8];
    const float* rb0  = (const float*)d_in[9];
    const float* rw1  = (const float*)d_in[10];
    const float* rb1  = (const float*)d_in[11];
    const float* rwt0 = (const float*)d_in[12];
    const float* rbt0 = (const float*)d_in[13];
    const float* rw2  = (const float*)d_in[14];
    const float* rb2  = (const float*)d_in[15];
    const float* rwt1 = (const float*)d_in[16];
    const float* rbt1 = (const float*)d_in[17];
    const float* rw3  = (const float*)d_in[18];
    const float* rb3  = (const float*)d_in[19];
    const float* rwt2 = (const float*)d_in[20];
    const float* rbt2 = (const float*)d_in[21];
    float* out = (float*)d_out;

    k_init     <<<80, 256>>>(out);
    k_noise    <<<dim3(16, 8), 256>>>(feat, cw, cb, out);
    k_route0   <<<dim3(32, 4), 128>>>(feat, rw0, rb0);
    k_conv3_32 <<<80, 256>>>(rw1, rb1);
    k_convt_32 <<<320, 256>>>(rwt0, rbt0);
    k_conv3_64 <<<320, 256>>>(rw2, rb2);
    k_convt_64 <<<1280, 256>>>(rwt1, rbt1);
    k_conv3_128<<<1280, 256>>>(rw3, rb3);
    k_convt_128<<<5120, 256>>>(rwt2, rbt2);
    k_lbconv   <<<dim3(32, 4), 256>>>(feat, w1, b1);
    k_gemm     <<<527, 256>>>(w2, b2);
    k_reg      <<<8423, 256>>>();
    k_final    <<<1024, 256>>>(img, out);
    k_loss     <<<1, 1>>>(out);
}

// round 9
// speedup vs baseline: 1.0023x; 1.0023x over previous
#include <cuda_runtime.h>
#include <math.h>

typedef unsigned long long ull;

// ---------------------------------------------------------------------------
// Problem constants
// ---------------------------------------------------------------------------
#define BB    4
#define CINF  320
#define DD    33
#define KK    5
#define D2C   1089          // 33*33
#define D3C   35937         // 33^3
#define NJC   539055        // 3*D^3*K
#define LUTBK 107811        // 3*D^3  (stride per (b,k))
#define HWC   65536         // 256*256
#define NPIXC 262144        // B*H*W
#define NOISE_N 16384       // 4*4*32*32
#define OUT_LUT_OFF 16384
#define OUT_LOSS_OFF 802816
#define NREG  2156220       // B*K*3*D^3

// ---------------------------------------------------------------------------
// Scratch (static device globals: no allocation allowed)
// ---------------------------------------------------------------------------
__device__ float g_pooled[BB * 256];
__device__ float g_lut[BB * NJC];              // [B, K,3,D,D,D]
__device__ float g_r0 [BB * KK * 1024];
__device__ float g_r1 [BB * KK * 1024];
__device__ float g_rt0[BB * KK * 4096];
__device__ float g_r2 [BB * KK * 4096];
__device__ float g_rt1[BB * KK * 16384];
__device__ float g_r3 [BB * KK * 16384];
__device__ float g_rt2[BB * KK * 65536];
__device__ float g_acc[4];                     // tv, mn, wnorm

// ---------------------------------------------------------------------------
// Packed fp32x2 FMA: operands stay in 64-bit register pairs (no pack/unpack)
// ---------------------------------------------------------------------------
__device__ __forceinline__ ull ffma2u(ull a, ull b, ull c) {
    ull d;
    asm("fma.rn.f32x2 %0, %1, %2, %3;" : "=l"(d) : "l"(a), "l"(b), "l"(c));
    return d;
}
__device__ __forceinline__ float lo32f(ull v) {
    return __uint_as_float((unsigned)(v & 0xffffffffull));
}
__device__ __forceinline__ float hi32f(ull v) {
    return __uint_as_float((unsigned)(v >> 32));
}

// ---------------------------------------------------------------------------
// K0: zero noise region of out + accumulators
// ---------------------------------------------------------------------------
__global__ void k_init(float* __restrict__ out) {
    int i = blockIdx.x * 256 + threadIdx.x;
    if (i < NOISE_N) out[i] = 0.f;
    if (i < 4) g_acc[i] = 0.f;
}

// ---------------------------------------------------------------------------
// K1: noise_pred conv3x3 320->4 @32x32, split over cin groups (atomic adds)
// ---------------------------------------------------------------------------
__global__ void k_noise(const float* __restrict__ feat, const float* __restrict__ w,
                        const float* __restrict__ bias, float* __restrict__ out) {
    __shared__ float plane[1024];
    __shared__ float ws[9];
    const int bx = blockIdx.x;
    const int b = bx >> 2, co = bx & 3;
    const int g = blockIdx.y;
    const int t = threadIdx.x;
    const int row = t >> 3, col = (t & 7) << 2;
    float bv = (g == 0) ? bias[co] : 0.f;
    float a0 = bv, a1 = bv, a2 = bv, a3 = bv;
    for (int ci = 0; ci < 40; ++ci) {
        const int cin = g * 40 + ci;
        reinterpret_cast<float4*>(plane)[t] =
            reinterpret_cast<const float4*>(feat + ((size_t)(b * CINF + cin) << 10))[t];
        if (t < 9) ws[t] = w[(co * CINF + cin) * 9 + t];
        __syncthreads();
#pragma unroll
        for (int ky = 0; ky < 3; ++ky) {
            const int r = row + ky - 1;
            if ((unsigned)r < 32u) {
                float v[6];
#pragma unroll
                for (int i = 0; i < 6; ++i) {
                    int c = col + i - 1;
                    v[i] = ((unsigned)c < 32u) ? plane[(r << 5) + c] : 0.f;
                }
#pragma unroll
                for (int kx = 0; kx < 3; ++kx) {
                    const float wv = ws[ky * 3 + kx];
                    a0 += wv * v[kx];     a1 += wv * v[kx + 1];
                    a2 += wv * v[kx + 2]; a3 += wv * v[kx + 3];
                }
            }
        }
        __syncthreads();
    }
    float* o = out + ((b * 4 + co) << 10) + (row << 5) + col;
    atomicAdd(o + 0, a0); atomicAdd(o + 1, a1);
    atomicAdd(o + 2, a2); atomicAdd(o + 3, a3);
}

// ---------------------------------------------------------------------------
// K2: lut-branch conv3x3 320->256 + bias + relu + global avg pool -> pooled
// FFMA2 version: thread = 4 consecutive px (2 packed pairs) x 8 couts.
// All packed operands live as ull (register pairs); odd pairs built once per
// (cin,ky) and shared by all couts. grid: (32 cout-groups of 8, 4 b), block 256
// ---------------------------------------------------------------------------
__global__ void k_lbconv(const float* __restrict__ feat, const float* __restrict__ w1,
                         const float* __restrict__ b1) {
    __shared__ __align__(16) float plane[1024];
    __shared__ ull ws2[72];                    // 8 couts x 9 taps, (w,w) packed
    __shared__ float wred[8][8];
    const int b = blockIdx.y;
    const int co0 = blockIdx.x << 3;
    const int t = threadIdx.x;
    const int row = t >> 3, col0 = (t & 7) << 2;   // 4 px per thread

    ull acc[8][2];
#pragma unroll
    for (int co = 0; co < 8; ++co) { acc[co][0] = 0ull; acc[co][1] = 0ull; }

    for (int cin = 0; cin < CINF; ++cin) {
        reinterpret_cast<float4*>(plane)[t] =
            reinterpret_cast<const float4*>(feat + ((size_t)(b * CINF + cin) << 10))[t];
        if (t < 72) {
            const unsigned u = __float_as_uint(
                w1[((co0 + t / 9) * CINF + cin) * 9 + (t % 9)]);
            ws2[t] = (ull)u | ((ull)u << 32);
        }
        __syncthreads();
#pragma unroll
        for (int ky = 0; ky < 3; ++ky) {
            const int rr = row + ky - 1;
            if ((unsigned)rr < 32u) {
                const float* rp = plane + (rr << 5) + col0;
                const ull E0 = *reinterpret_cast<const ull*>(rp);      // px0,px1
                const ull E1 = *reinterpret_cast<const ull*>(rp + 2);  // px2,px3
                const float vm1 = (col0 > 0)  ? rp[-1] : 0.f;
                const float v4  = (col0 < 28) ? rp[4]  : 0.f;
                const ull O0 = (ull)__float_as_uint(vm1) | (E0 << 32); // px-1,px0
                const ull O1 = (E0 >> 32) | (E1 << 32);                // px1,px2
                const ull O2 = (E1 >> 32) | ((ull)__float_as_uint(v4) << 32); // px3,px4
#pragma unroll
                for (int co = 0; co < 8; ++co) {
                    const int wb = co * 9 + ky * 3;
                    const ull w0 = ws2[wb + 0];
                    const ull wA = ws2[wb + 1];
                    const ull wB = ws2[wb + 2];
                    acc[co][0] = ffma2u(O0, w0, acc[co][0]);
                    acc[co][0] = ffma2u(E0, wA, acc[co][0]);
                    acc[co][0] = ffma2u(O1, wB, acc[co][0]);
                    acc[co][1] = ffma2u(O1, w0, acc[co][1]);
                    acc[co][1] = ffma2u(E1, wA, acc[co][1]);
                    acc[co][1] = ffma2u(O2, wB, acc[co][1]);
                }
            }
        }
        __syncthreads();
    }

    const int lane = t & 31, wp = t >> 5;
#pragma unroll
    for (int co = 0; co < 8; ++co) {
        const float bv = b1[co0 + co];
        float s = fmaxf(lo32f(acc[co][0]) + bv, 0.f) + fmaxf(hi32f(acc[co][0]) + bv, 0.f)
                + fmaxf(lo32f(acc[co][1]) + bv, 0.f) + fmaxf(hi32f(acc[co][1]) + bv, 0.f);
#pragma unroll
        for (int o = 16; o > 0; o >>= 1) s += __shfl_xor_sync(0xffffffffu, s, o);
        if (lane == 0) wred[wp][co] = s;
    }
    __syncthreads();
    if (t < 8) {
        float s = 0.f;
#pragma unroll
        for (int i = 0; i < 8; ++i) s += wred[i][t];
        g_pooled[b * 256 + co0 + t] = s * (1.f / 1024.f);
    }
}

// ---------------------------------------------------------------------------
// K3: lut_params[b,j] = pooled[b,:] . w2[j,:] + b2[j]   (DRAM-bound: 552 MB)
// ---------------------------------------------------------------------------
__global__ void k_gemm(const float* __restrict__ w2, const float* __restrict__ b2) {
    __shared__ __align__(16) float sp[1024];
    const int t = threadIdx.x;
#pragma unroll
    for (int i = 0; i < 4; ++i) sp[t + (i << 8)] = g_pooled[t + (i << 8)];
    __syncthreads();
    const int jb = (blockIdx.x << 10) + t;
    float acc[4][4];
#pragma unroll
    for (int i = 0; i < 4; ++i)
#pragma unroll
        for (int q = 0; q < 4; ++q) acc[i][q] = 0.f;
    const float4* w2v = reinterpret_cast<const float4*>(w2);
#pragma unroll 2
    for (int c4 = 0; c4 < 64; ++c4) {
        const float4 p0 = *reinterpret_cast<const float4*>(sp + (c4 << 2));
        const float4 p1 = *reinterpret_cast<const float4*>(sp + 256 + (c4 << 2));
        const float4 p2 = *reinterpret_cast<const float4*>(sp + 512 + (c4 << 2));
        const float4 p3 = *reinterpret_cast<const float4*>(sp + 768 + (c4 << 2));
#pragma unroll
        for (int i = 0; i < 4; ++i) {
            const int j = jb + (i << 8);
            if (j < NJC) {
                const float4 wv = __ldg(w2v + (size_t)j * 64 + c4);
                acc[i][0] += wv.x * p0.x + wv.y * p0.y + wv.z * p0.z + wv.w * p0.w;
                acc[i][1] += wv.x * p1.x + wv.y * p1.y + wv.z * p1.z + wv.w * p1.w;
                acc[i][2] += wv.x * p2.x + wv.y * p2.y + wv.z * p2.z + wv.w * p2.w;
                acc[i][3] += wv.x * p3.x + wv.y * p3.y + wv.z * p3.z + wv.w * p3.w;
            }
        }
    }
#pragma unroll
    for (int i = 0; i < 4; ++i) {
        const int j = jb + (i << 8);
        if (j < NJC) {
            const float bv = b2[j];
#pragma unroll
            for (int q = 0; q < 4; ++q) g_lut[(size_t)q * NJC + j] = acc[i][q] + bv;
        }
    }
}

// ---------------------------------------------------------------------------
// Routing network
// ---------------------------------------------------------------------------
__global__ void k_route0(const float* __restrict__ feat, const float* __restrict__ w0,
                         const float* __restrict__ b0) {
    const int idx = blockIdx.x * 256 + threadIdx.x;   // < 20480
    const int p = idx & 1023;
    const int bk = idx >> 10;
    const int k = bk % KK, b = bk / KK;
    float acc = b0[k];
    const float* f = feat + ((size_t)(b * CINF) << 10) + p;
    const float* w = w0 + k * CINF;
#pragma unroll 8
    for (int c = 0; c < CINF; ++c) acc += f[(size_t)c << 10] * __ldg(w + c);
    g_r0[idx] = fmaxf(acc, 0.f);
}

template <int S>
__device__ __forceinline__ void conv3_impl(const float* __restrict__ in,
                                           const float* __restrict__ w,
                                           const float* __restrict__ bias,
                                           float* __restrict__ outp) {
    const int idx = blockIdx.x * 256 + threadIdx.x;
    if (idx >= BB * KK * S * S) return;
    const int x = idx % S;
    const int y = (idx / S) % S;
    const int k = (idx / (S * S)) % KK;
    const int b = idx / (S * S * KK);
    float acc = bias[k];
#pragma unroll
    for (int c = 0; c < KK; ++c) {
        const float* ip = in + (size_t)(b * KK + c) * S * S;
        const float* wp = w + (k * KK + c) * 9;
#pragma unroll
        for (int ky = 0; ky < 3; ++ky) {
            const int yy = y + ky - 1;
            if ((unsigned)yy < (unsigned)S) {
#pragma unroll
                for (int kx = 0; kx < 3; ++kx) {
                    const int xx = x + kx - 1;
                    if ((unsigned)xx < (unsigned)S)
                        acc += ip[yy * S + xx] * __ldg(wp + ky * 3 + kx);
                }
            }
        }
    }
    outp[idx] = fmaxf(acc, 0.f);
}

template <int Sin>
__device__ __forceinline__ void convT_impl(const float* __restrict__ in,
                                           const float* __restrict__ w,
                                           const float* __restrict__ bias,
                                           float* __restrict__ outp) {
    constexpr int So = 2 * Sin;
    const int idx = blockIdx.x * 256 + threadIdx.x;
    if (idx >= BB * KK * So * So) return;
    const int ox = idx % So;
    const int oy = (idx / So) % So;
    const int k = (idx / (So * So)) % KK;
    const int b = idx / (So * So * KK);
    float acc = bias[k];
    const int py = (oy + 1) & 1, px = (ox + 1) & 1;
#pragma unroll
    for (int c = 0; c < KK; ++c) {
        const float* ip = in + (size_t)(b * KK + c) * Sin * Sin;
        const float* wp = w + (c * KK + k) * 16;
#pragma unroll
        for (int jy = 0; jy < 2; ++jy) {
            const int ky = py + 2 * jy;
            const int ny = oy + 1 - ky;
            const int iy = ny >> 1;
            if (ny >= 0 && iy < Sin) {
#pragma unroll
                for (int jx = 0; jx < 2; ++jx) {
                    const int kx = px + 2 * jx;
                    const int nx = ox + 1 - kx;
                    const int ix = nx >> 1;
                    if (nx >= 0 && ix < Sin)
                        acc += ip[iy * Sin + ix] * __ldg(wp + ky * 4 + kx);
                }
            }
        }
    }
    outp[idx] = acc;
}

__global__ void k_conv3_32 (const float* w, const float* b) { conv3_impl<32> (g_r0,  w, b, g_r1 ); }
__global__ void k_convt_32 (const float* w, const float* b) { convT_impl<32> (g_r1,  w, b, g_rt0); }
__global__ void k_conv3_64 (const float* w, const float* b) { conv3_impl<64> (g_rt0, w, b, g_r2 ); }
__global__ void k_convt_64 (const float* w, const float* b) { convT_impl<64> (g_r2,  w, b, g_rt1); }
__global__ void k_conv3_128(const float* w, const float* b) { conv3_impl<128>(g_rt1, w, b, g_r3 ); }
__global__ void k_convt_128(const float* w, const float* b) { convT_impl<128>(g_r3,  w, b, g_rt2); }

// ---------------------------------------------------------------------------
// K5: TV + monotonicity regularizers over g_lut (single pass, fused dirs)
// ---------------------------------------------------------------------------
__global__ void k_reg() {
    const int idx = blockIdx.x * 256 + threadIdx.x;
    float tv = 0.f, mn = 0.f;
    if (idx < NREG) {
        const int x = idx % 33;
        const int r1 = idx / 33;
        const int y = r1 % 33;
        const int z = (r1 / 33) % 33;
        const float v = g_lut[idx];
        if (x < 32) {
            const float d = v - g_lut[idx + 1];
            const float w = (x == 0 || x == 31) ? 2.f : 1.f;
            tv += d * d * w; mn += fmaxf(d, 0.f);
        }
        if (y < 32) {
            const float d = v - g_lut[idx + 33];
            const float w = (y == 0 || y == 31) ? 2.f : 1.f;
            tv += d * d * w; mn += fmaxf(d, 0.f);
        }
        if (z < 32) {
            const float d = v - g_lut[idx + 1089];
            const float w = (z == 0 || z == 31) ? 2.f : 1.f;
            tv += d * d * w; mn += fmaxf(d, 0.f);
        }
    }
#pragma unroll
    for (int o = 16; o > 0; o >>= 1) {
        tv += __shfl_xor_sync(0xffffffffu, tv, o);
        mn += __shfl_xor_sync(0xffffffffu, mn, o);
    }
    __shared__ float stv[8], smn[8];
    const int lane = threadIdx.x & 31, wp = threadIdx.x >> 5;
    if (lane == 0) { stv[wp] = tv; smn[wp] = mn; }
    __syncthreads();
    if (threadIdx.x == 0) {
        float a = 0.f, m = 0.f;
#pragma unroll
        for (int i = 0; i < 8; ++i) { a += stv[i]; m += smn[i]; }
        atomicAdd(&g_acc[0], a);
        atomicAdd(&g_acc[1], m);
    }
}

// ---------------------------------------------------------------------------
// K6: softmax routing + trilinear LUT blend + weights_norm  (1 thread/pixel)
// ---------------------------------------------------------------------------
__global__ void k_final(const float* __restrict__ img, float* __restrict__ out) {
    const int pix = blockIdx.x * 256 + threadIdx.x;  // exactly NPIXC threads
    const int b = pix >> 16;
    const int p = pix & 0xFFFF;

    const float rn = img[(size_t)(b * 3 + 0) * HWC + p] * 0.5f + 0.5f;
    const float gn = img[(size_t)(b * 3 + 1) * HWC + p] * 0.5f + 0.5f;
    const float bn = img[(size_t)(b * 3 + 2) * HWC + p] * 0.5f + 0.5f;
    const float cx = fminf(fmaxf(rn * 32.f, 0.f), 32.f);
    const float cy = fminf(fmaxf(gn * 32.f, 0.f), 32.f);
    const float cz = fminf(fmaxf(bn * 32.f, 0.f), 32.f);
    const int x0 = min((int)cx, 31);
    const int y0 = min((int)cy, 31);
    const int z0 = min((int)cz, 31);
    const float xd = cx - (float)x0, yd = cy - (float)y0, zd = cz - (float)z0;

    float rv[5];
    const float* rf = g_rt2 + (size_t)(b * KK) * HWC + p;
    float m = -1e30f;
#pragma unroll
    for (int k = 0; k < KK; ++k) { rv[k] = rf[(size_t)k * HWC]; m = fmaxf(m, rv[k]); }
    float se = 0.f;
#pragma unroll
    for (int k = 0; k < KK; ++k) { rv[k] = expf(rv[k] - m); se += rv[k]; }
    const float inv = 1.f / se;

    const int o000 = z0 * D2C + y0 * 33 + x0;
    float a0 = 0.f, a1 = 0.f, a2 = 0.f, wn = 0.f;
#pragma unroll
    for (int k = 0; k < KK; ++k) {
        const float pw = rv[k] * inv;
        wn += pw * pw;
        const float* L = g_lut + (size_t)(b * KK + k) * LUTBK + o000;
#pragma unroll
        for (int ch = 0; ch < 3; ++ch) {
            const float* Lc = L + ch * D3C;
            const float c000 = Lc[0],    c001 = Lc[1];
            const float c010 = Lc[33],   c011 = Lc[34];
            const float c100 = Lc[1089], c101 = Lc[1090];
            const float c110 = Lc[1122], c111 = Lc[1123];
            const float c00 = c000 + (c001 - c000) * xd;
            const float c01 = c010 + (c011 - c010) * xd;
            const float c10 = c100 + (c101 - c100) * xd;
            const float c11 = c110 + (c111 - c110) * xd;
            const float c0 = c00 + (c01 - c00) * yd;
            const float c1 = c10 + (c11 - c10) * yd;
            const float val = c0 + (c1 - c0) * zd;
            if (ch == 0) a0 += val * pw;
            else if (ch == 1) a1 += val * pw;
            else a2 += val * pw;
        }
    }
    out[OUT_LUT_OFF + (size_t)(b * 3 + 0) * HWC + p] = a0;
    out[OUT_LUT_OFF + (size_t)(b * 3 + 1) * HWC + p] = a1;
    out[OUT_LUT_OFF + (size_t)(b * 3 + 2) * HWC + p] = a2;

#pragma unroll
    for (int o = 16; o > 0; o >>= 1) wn += __shfl_xor_sync(0xffffffffu, wn, o);
    __shared__ float swn[8];
    const int lane = threadIdx.x & 31, wp = threadIdx.x >> 5;
    if (lane == 0) swn[wp] = wn;
    __syncthreads();
    if (threadIdx.x == 0) {
        float s = 0.f;
#pragma unroll
        for (int i = 0; i < 8; ++i) s += swn[i];
        atomicAdd(&g_acc[2], s);
    }
}

// ---------------------------------------------------------------------------
// K7: combine regularizers into reg_loss
// ---------------------------------------------------------------------------
__global__ void k_loss(float* __restrict__ out) {
    const float tv = g_acc[0] * (1.f / 104544.f);   // 3*33*33*32
    const float mn = g_acc[1] * (1.f / 104544.f);
    const float wn = g_acc[2] * (1.f / 1310720.f);  // 4*5*256*256
    out[OUT_LOSS_OFF] = 0.0005f * (wn + tv * 0.25f) + 10.f * (mn * 0.25f);
}

// ---------------------------------------------------------------------------
extern "C" void kernel_launch(void* const* d_in, const int* in_sizes, int n_in,
                              void* d_out, int out_size) {
    const float* feat = (const float*)d_in[0];
    const float* img  = (const float*)d_in[1];
    const float* cw   = (const float*)d_in[2];
    const float* cb   = (const float*)d_in[3];
    const float* w1   = (const float*)d_in[4];
    const float* b1   = (const float*)d_in[5];
    const float* w2   = (const float*)d_in[6];
    const float* b2   = (const float*)d_in[7];
    const float* rw0  = (const float*)d_in[8];
    const float* rb0  = (const float*)d_in[9];
    const float* rw1  = (const float*)d_in[10];
    const float* rb1  = (const float*)d_in[11];
    const float* rwt0 = (const float*)d_in[12];
    const float* rbt0 = (const float*)d_in[13];
    const float* rw2  = (const float*)d_in[14];
    const float* rb2  = (const float*)d_in[15];
    const float* rwt1 = (const float*)d_in[16];
    const float* rbt1 = (const float*)d_in[17];
    const float* rw3  = (const float*)d_in[18];
    const float* rb3  = (const float*)d_in[19];
    const float* rwt2 = (const float*)d_in[20];
    const float* rbt2 = (const float*)d_in[21];
    float* out = (float*)d_out;

    k_init     <<<65, 256>>>(out);
    k_noise    <<<dim3(16, 8), 256>>>(feat, cw, cb, out);
    k_lbconv   <<<dim3(32, 4), 256>>>(feat, w1, b1);
    k_route0   <<<80, 256>>>(feat, rw0, rb0);
    k_conv3_32 <<<80, 256>>>(rw1, rb1);
    k_convt_32 <<<320, 256>>>(rwt0, rbt0);
    k_conv3_64 <<<320, 256>>>(rw2, rb2);
    k_convt_64 <<<1280, 256>>>(rwt1, rbt1);
    k_conv3_128<<<1280, 256>>>(rw3, rb3);
    k_convt_128<<<5120, 256>>>(rwt2, rbt2);
    k_gemm     <<<527, 256>>>(w2, b2);
    k_reg      <<<8423, 256>>>();
    k_final    <<<1024, 256>>>(img, out);
    k_loss     <<<1, 1>>>(out);
}

// round 10
// speedup vs baseline: 1.5872x; 1.5835x over previous
#include <cuda_runtime.h>
#include <math.h>

// ---------------------------------------------------------------------------
// Problem constants
// ---------------------------------------------------------------------------
#define BB    4
#define CINF  320
#define DD    33
#define KK    5
#define D2C   1089          // 33*33
#define D3C   35937         // 33^3
#define NJC   539055        // 3*D^3*K
#define LUTBK 107811        // 3*D^3  (stride per (b,k))
#define HWC   65536         // 256*256
#define NPIXC 262144        // B*H*W
#define NOISE_N 16384       // 4*4*32*32
#define OUT_LUT_OFF 16384
#define OUT_LOSS_OFF 802816
#define NREG  2156220       // B*K*3*D^3

#define KDIM  2880          // 320*9 im2col depth
#define MROWS 4096          // 4 * 1024 pixels

// ---------------------------------------------------------------------------
// Scratch (static device globals: no allocation allowed)
// ---------------------------------------------------------------------------
__device__ float g_pooled[BB * 256];
__device__ float g_lut[BB * NJC];              // [B, K,3,D,D,D]
__device__ float g_r0 [BB * KK * 1024];        // raw (pre-relu) routing conv0
__device__ float g_r1 [BB * KK * 1024];
__device__ float g_rt0[BB * KK * 4096];
__device__ float g_r2 [BB * KK * 4096];
__device__ float g_rt1[BB * KK * 16384];
__device__ float g_r3 [BB * KK * 16384];
__device__ float g_rt2[BB * KK * 65536];
__device__ float g_acc[4];                     // tv, mn, wnorm
__device__ float g_A [MROWS * KDIM];           // im2col (tf32-rounded), 47.2 MB
__device__ float g_Wt[KDIM * 256];             // transposed conv weights (tf32)

// ---------------------------------------------------------------------------
// tf32 helpers
// ---------------------------------------------------------------------------
__device__ __forceinline__ float f2tf32(float f) {
    unsigned u;
    asm("cvt.rna.tf32.f32 %0, %1;" : "=r"(u) : "f"(f));
    return __uint_as_float(u);
}

__device__ __forceinline__ void mma_tf32(float* c, float a0, float a1, float a2,
                                         float a3, float b0, float b1) {
    asm("mma.sync.aligned.m16n8k8.row.col.f32.tf32.tf32.f32 "
        "{%0,%1,%2,%3}, {%4,%5,%6,%7}, {%8,%9}, {%0,%1,%2,%3};"
        : "+f"(c[0]), "+f"(c[1]), "+f"(c[2]), "+f"(c[3])
        : "r"(__float_as_uint(a0)), "r"(__float_as_uint(a1)),
          "r"(__float_as_uint(a2)), "r"(__float_as_uint(a3)),
          "r"(__float_as_uint(b0)), "r"(__float_as_uint(b1)));
}

// ---------------------------------------------------------------------------
// K0: zero out-noise region, routing raw buffer, pooled, accumulators
// ---------------------------------------------------------------------------
__global__ void k_init(float* __restrict__ out) {
    int i = blockIdx.x * 256 + threadIdx.x;   // 20480 threads
    if (i < NOISE_N) out[i] = 0.f;
    if (i < BB * KK * 1024) g_r0[i] = 0.f;
    if (i < BB * 256) g_pooled[i] = 0.f;
    if (i < 4) g_acc[i] = 0.f;
}

// ---------------------------------------------------------------------------
// K1: noise_pred conv3x3 320->4 @32x32, split over cin groups (atomic adds)
// ---------------------------------------------------------------------------
__global__ void k_noise(const float* __restrict__ feat, const float* __restrict__ w,
                        const float* __restrict__ bias, float* __restrict__ out) {
    __shared__ float plane[1024];
    __shared__ float ws[9];
    const int bx = blockIdx.x;
    const int b = bx >> 2, co = bx & 3;
    const int g = blockIdx.y;
    const int t = threadIdx.x;
    const int row = t >> 3, col = (t & 7) << 2;
    float bv = (g == 0) ? bias[co] : 0.f;
    float a0 = bv, a1 = bv, a2 = bv, a3 = bv;
    for (int ci = 0; ci < 40; ++ci) {
        const int cin = g * 40 + ci;
        reinterpret_cast<float4*>(plane)[t] =
            reinterpret_cast<const float4*>(feat + ((size_t)(b * CINF + cin) << 10))[t];
        if (t < 9) ws[t] = w[(co * CINF + cin) * 9 + t];
        __syncthreads();
#pragma unroll
        for (int ky = 0; ky < 3; ++ky) {
            const int r = row + ky - 1;
            if ((unsigned)r < 32u) {
                float v[6];
#pragma unroll
                for (int i = 0; i < 6; ++i) {
                    int c = col + i - 1;
                    v[i] = ((unsigned)c < 32u) ? plane[(r << 5) + c] : 0.f;
                }
#pragma unroll
                for (int kx = 0; kx < 3; ++kx) {
                    const float wv = ws[ky * 3 + kx];
                    a0 += wv * v[kx];     a1 += wv * v[kx + 1];
                    a2 += wv * v[kx + 2]; a3 += wv * v[kx + 3];
                }
            }
        }
        __syncthreads();
    }
    float* o = out + ((b * 4 + co) << 10) + (row << 5) + col;
    atomicAdd(o + 0, a0); atomicAdd(o + 1, a1);
    atomicAdd(o + 2, a2); atomicAdd(o + 3, a3);
}

// ---------------------------------------------------------------------------
// K2a: im2col of feat into g_A[4096][2880], tf32-rounded.
// One float4 per thread. grid 11520 x 256.
// ---------------------------------------------------------------------------
__global__ void k_im2col(const float* __restrict__ feat) {
    const int i4 = blockIdx.x * 256 + threadIdx.x;     // < 2949120
    const int base = i4 << 2;
    const int row = base / KDIM;
    const int k0 = base - row * KDIM;
    const int b = row >> 10;
    const int px = row & 1023;
    const int py = px >> 5, pxx = px & 31;
    float4 v;
    float* vp = &v.x;
#pragma unroll
    for (int q = 0; q < 4; ++q) {
        const int k = k0 + q;
        const int cin = k / 9;
        const int tt = k - cin * 9;
        const int ky = tt / 3, kx = tt - ky * 3;
        const int y = py + ky - 1, x = pxx + kx - 1;
        float val = 0.f;
        if ((unsigned)y < 32u && (unsigned)x < 32u)
            val = __ldg(feat + ((size_t)(b * CINF + cin) << 10) + (y << 5) + x);
        vp[q] = f2tf32(val);
    }
    *reinterpret_cast<float4*>(g_A + base) = v;
}

// ---------------------------------------------------------------------------
// K2b: transpose conv weights -> g_Wt[k][n], tf32-rounded. grid 2880 x 256.
// ---------------------------------------------------------------------------
__global__ void k_wt(const float* __restrict__ w1) {
    const int i = blockIdx.x * 256 + threadIdx.x;      // < 737280
    const int k = i >> 8, n = i & 255;
    const int cin = k / 9, tt = k - cin * 9;
    g_Wt[i] = f2tf32(__ldg(w1 + (n * CINF + cin) * 9 + tt));
}

// ---------------------------------------------------------------------------
// K2c: tf32 tensor-core GEMM C[4096x256] = A @ Wt, fused bias+relu+pool.
// CTA: 32 rows x 256 cols, 8 warps (2M x 4N), warp tile m16 x n64.
// K chunk 16, double-buffered smem. grid 128 x 256.
// ---------------------------------------------------------------------------
#define AST 20     // As row stride (pad: conflict-free frag loads)
#define BST 264    // Bs row stride (pad: conflict-free frag loads)
#define NCHUNK 180 // 2880/16

__global__ void k_lbmma(const float* __restrict__ b1) {
    __shared__ __align__(16) float As[2][32 * AST];
    __shared__ __align__(16) float Bs[2][16 * BST];
    const int t = threadIdx.x;
    const int cta = blockIdx.x;
    const int b = cta >> 5;
    const int m0 = (cta & 31) << 5;
    const int row_g = (b << 10) + m0;
    const int warp = t >> 5, lane = t & 31;
    const int wm = warp >> 2, wn = warp & 3;
    const int g = lane >> 2, tg = lane & 3;

    float C[8][4];
#pragma unroll
    for (int j = 0; j < 8; ++j)
#pragma unroll
        for (int q = 0; q < 4; ++q) C[j][q] = 0.f;

    // load indices: A (t<128): arow=t>>2, af4=t&3 ; B: 4 f4/thread
    const int arow = t >> 2, af4 = t & 3;

    // preload chunk 0
    if (t < 128) {
        float4 v = *reinterpret_cast<const float4*>(
            g_A + (size_t)(row_g + arow) * KDIM + (af4 << 2));
        *reinterpret_cast<float4*>(&As[0][arow * AST + (af4 << 2)]) = v;
    }
#pragma unroll
    for (int j = 0; j < 4; ++j) {
        const int lin = j * 256 + t;          // < 1024
        const int krow = lin >> 6, bf4 = lin & 63;
        float4 v = *reinterpret_cast<const float4*>(g_Wt + krow * 256 + (bf4 << 2));
        *reinterpret_cast<float4*>(&Bs[0][krow * BST + (bf4 << 2)]) = v;
    }
    __syncthreads();

    int buf = 0;
    for (int c = 0; c < NCHUNK; ++c) {
        float4 ra;
        float4 rb[4];
        if (c < NCHUNK - 1) {
            const int kc = (c + 1) << 4;
            if (t < 128)
                ra = *reinterpret_cast<const float4*>(
                    g_A + (size_t)(row_g + arow) * KDIM + kc + (af4 << 2));
#pragma unroll
            for (int j = 0; j < 4; ++j) {
                const int lin = j * 256 + t;
                const int krow = lin >> 6, bf4 = lin & 63;
                rb[j] = *reinterpret_cast<const float4*>(
                    g_Wt + (size_t)(kc + krow) * 256 + (bf4 << 2));
            }
        }
        // compute on buf
        const float* as = As[buf];
        const float* bs = Bs[buf];
#pragma unroll
        for (int kq = 0; kq < 2; ++kq) {
            const int kk = kq << 3;
            const int ar = (wm << 4) + g;
            const float a0 = as[ar * AST + kk + tg];
            const float a1 = as[(ar + 8) * AST + kk + tg];
            const float a2 = as[ar * AST + kk + tg + 4];
            const float a3 = as[(ar + 8) * AST + kk + tg + 4];
#pragma unroll
            for (int j = 0; j < 8; ++j) {
                const int n0 = (wn << 6) + (j << 3);
                const float b0 = bs[(kk + tg) * BST + n0 + g];
                const float b1 = bs[(kk + tg + 4) * BST + n0 + g];
                mma_tf32(C[j], a0, a1, a2, a3, b0, b1);
            }
        }
        if (c < NCHUNK - 1) {
            if (t < 128)
                *reinterpret_cast<float4*>(&As[buf ^ 1][arow * AST + (af4 << 2)]) = ra;
#pragma unroll
            for (int j = 0; j < 4; ++j) {
                const int lin = j * 256 + t;
                const int krow = lin >> 6, bf4 = lin & 63;
                *reinterpret_cast<float4*>(&Bs[buf ^ 1][krow * BST + (bf4 << 2)]) = rb[j];
            }
        }
        __syncthreads();
        buf ^= 1;
    }

    // epilogue: bias + relu + column sums -> g_pooled (mean via 1/1024)
#pragma unroll
    for (int j = 0; j < 8; ++j) {
        const int n0 = (wn << 6) + (j << 3);
        const float bv0 = __ldg(b1 + n0 + (tg << 1));
        const float bv1 = __ldg(b1 + n0 + (tg << 1) + 1);
        float s0 = fmaxf(C[j][0] + bv0, 0.f) + fmaxf(C[j][2] + bv0, 0.f);
        float s1 = fmaxf(C[j][1] + bv1, 0.f) + fmaxf(C[j][3] + bv1, 0.f);
#pragma unroll
        for (int o = 4; o <= 16; o <<= 1) {
            s0 += __shfl_xor_sync(0xffffffffu, s0, o);
            s1 += __shfl_xor_sync(0xffffffffu, s1, o);
        }
        if (g == 0) {
            atomicAdd(&g_pooled[(b << 8) + n0 + (tg << 1)],     s0 * (1.f / 1024.f));
            atomicAdd(&g_pooled[(b << 8) + n0 + (tg << 1) + 1], s1 * (1.f / 1024.f));
        }
    }
}

// ---------------------------------------------------------------------------
// K3: lut_params[b,j] = pooled[b,:] . w2[j,:] + b2[j]   (DRAM-bound: 552 MB)
// ---------------------------------------------------------------------------
__global__ void k_gemm(const float* __restrict__ w2, const float* __restrict__ b2) {
    __shared__ __align__(16) float sp[1024];
    const int t = threadIdx.x;
#pragma unroll
    for (int i = 0; i < 4; ++i) sp[t + (i << 8)] = g_pooled[t + (i << 8)];
    __syncthreads();
    const int jb = (blockIdx.x << 10) + t;
    float acc[4][4];
#pragma unroll
    for (int i = 0; i < 4; ++i)
#pragma unroll
        for (int q = 0; q < 4; ++q) acc[i][q] = 0.f;
    const float4* w2v = reinterpret_cast<const float4*>(w2);
#pragma unroll 2
    for (int c4 = 0; c4 < 64; ++c4) {
        const float4 p0 = *reinterpret_cast<const float4*>(sp + (c4 << 2));
        const float4 p1 = *reinterpret_cast<const float4*>(sp + 256 + (c4 << 2));
        const float4 p2 = *reinterpret_cast<const float4*>(sp + 512 + (c4 << 2));
        const float4 p3 = *reinterpret_cast<const float4*>(sp + 768 + (c4 << 2));
#pragma unroll
        for (int i = 0; i < 4; ++i) {
            const int j = jb + (i << 8);
            if (j < NJC) {
                const float4 wv = __ldg(w2v + (size_t)j * 64 + c4);
                acc[i][0] += wv.x * p0.x + wv.y * p0.y + wv.z * p0.z + wv.w * p0.w;
                acc[i][1] += wv.x * p1.x + wv.y * p1.y + wv.z * p1.z + wv.w * p1.w;
                acc[i][2] += wv.x * p2.x + wv.y * p2.y + wv.z * p2.z + wv.w * p2.w;
                acc[i][3] += wv.x * p3.x + wv.y * p3.y + wv.z * p3.z + wv.w * p3.w;
            }
        }
    }
#pragma unroll
    for (int i = 0; i < 4; ++i) {
        const int j = jb + (i << 8);
        if (j < NJC) {
            const float bv = b2[j];
#pragma unroll
            for (int q = 0; q < 4; ++q) g_lut[(size_t)q * NJC + j] = acc[i][q] + bv;
        }
    }
}

// ---------------------------------------------------------------------------
// Routing conv0: thread = 1 pixel, all 5 experts; cin split into 4 groups of
// 80 (atomics into zeroed g_r0; relu deferred to k_conv3_32's load).
// grid (32, 4), block 128
// ---------------------------------------------------------------------------
__global__ void k_route0(const float* __restrict__ feat, const float* __restrict__ w0,
                         const float* __restrict__ b0) {
    const int t = threadIdx.x;
    const int gp = blockIdx.x * 128 + t;   // 0..4095 = b*1024 + p
    const int b = gp >> 10, p = gp & 1023;
    const int c0 = blockIdx.y * 80;
    float acc[KK];
#pragma unroll
    for (int k = 0; k < KK; ++k) acc[k] = 0.f;
    const float* f = feat + ((size_t)(b * CINF + c0) << 10) + p;
#pragma unroll 8
    for (int c = 0; c < 80; ++c) {
        const float v = f[(size_t)c << 10];
#pragma unroll
        for (int k = 0; k < KK; ++k) acc[k] += v * __ldg(w0 + k * CINF + c0 + c);
    }
    if (blockIdx.y == 0) {
#pragma unroll
        for (int k = 0; k < KK; ++k) acc[k] += b0[k];
    }
#pragma unroll
    for (int k = 0; k < KK; ++k)
        atomicAdd(&g_r0[((b * KK + k) << 10) + p], acc[k]);
}

template <int S, bool RELU_IN>
__device__ __forceinline__ void conv3_impl(const float* __restrict__ in,
                                           const float* __restrict__ w,
                                           const float* __restrict__ bias,
                                           float* __restrict__ outp) {
    const int idx = blockIdx.x * 256 + threadIdx.x;
    if (idx >= BB * KK * S * S) return;
    const int x = idx % S;
    const int y = (idx / S) % S;
    const int k = (idx / (S * S)) % KK;
    const int b = idx / (S * S * KK);
    float acc = bias[k];
#pragma unroll
    for (int c = 0; c < KK; ++c) {
        const float* ip = in + (size_t)(b * KK + c) * S * S;
        const float* wp = w + (k * KK + c) * 9;
#pragma unroll
        for (int ky = 0; ky < 3; ++ky) {
            const int yy = y + ky - 1;
            if ((unsigned)yy < (unsigned)S) {
#pragma unroll
                for (int kx = 0; kx < 3; ++kx) {
                    const int xx = x + kx - 1;
                    if ((unsigned)xx < (unsigned)S) {
                        float v = ip[yy * S + xx];
                        if (RELU_IN) v = fmaxf(v, 0.f);
                        acc += v * __ldg(wp + ky * 3 + kx);
                    }
                }
            }
        }
    }
    outp[idx] = fmaxf(acc, 0.f);
}

template <int Sin>
__device__ __forceinline__ void convT_impl(const float* __restrict__ in,
                                           const float* __restrict__ w,
                                           const float* __restrict__ bias,
                                           float* __restrict__ outp) {
    constexpr int So = 2 * Sin;
    const int idx = blockIdx.x * 256 + threadIdx.x;
    if (idx >= BB * KK * So * So) return;
    const int ox = idx % So;
    const int oy = (idx / So) % So;
    const int k = (idx / (So * So)) % KK;
    const int b = idx / (So * So * KK);
    float acc = bias[k];
    const int py = (oy + 1) & 1, px = (ox + 1) & 1;
#pragma unroll
    for (int c = 0; c < KK; ++c) {
        const float* ip = in + (size_t)(b * KK + c) * Sin * Sin;
        const float* wp = w + (c * KK + k) * 16;
#pragma unroll
        for (int jy = 0; jy < 2; ++jy) {
            const int ky = py + 2 * jy;
            const int ny = oy + 1 - ky;
            const int iy = ny >> 1;
            if (ny >= 0 && iy < Sin) {
#pragma unroll
                for (int jx = 0; jx < 2; ++jx) {
                    const int kx = px + 2 * jx;
                    const int nx = ox + 1 - kx;
                    const int ix = nx >> 1;
                    if (nx >= 0 && ix < Sin)
                        acc += ip[iy * Sin + ix] * __ldg(wp + ky * 4 + kx);
                }
            }
        }
    }
    outp[idx] = acc;
}

__global__ void k_conv3_32 (const float* w, const float* b) { conv3_impl<32, true>  (g_r0,  w, b, g_r1 ); }
__global__ void k_convt_32 (const float* w, const float* b) { convT_impl<32>  (g_r1,  w, b, g_rt0); }
__global__ void k_conv3_64 (const float* w, const float* b) { conv3_impl<64, false> (g_rt0, w, b, g_r2 ); }
__global__ void k_convt_64 (const float* w, const float* b) { convT_impl<64>  (g_r2,  w, b, g_rt1); }
__global__ void k_conv3_128(const float* w, const float* b) { conv3_impl<128, false>(g_rt1, w, b, g_r3 ); }
__global__ void k_convt_128(const float* w, const float* b) { convT_impl<128> (g_r3,  w, b, g_rt2); }

// ---------------------------------------------------------------------------
// K5: TV + monotonicity regularizers over g_lut (single pass, fused dirs)
// ---------------------------------------------------------------------------
__global__ void k_reg() {
    const int idx = blockIdx.x * 256 + threadIdx.x;
    float tv = 0.f, mn = 0.f;
    if (idx < NREG) {
        const int x = idx % 33;
        const int r1 = idx / 33;
        const int y = r1 % 33;
        const int z = (r1 / 33) % 33;
        const float v = g_lut[idx];
        if (x < 32) {
            const float d = v - g_lut[idx + 1];
            const float w = (x == 0 || x == 31) ? 2.f : 1.f;
            tv += d * d * w; mn += fmaxf(d, 0.f);
        }
        if (y < 32) {
            const float d = v - g_lut[idx + 33];
            const float w = (y == 0 || y == 31) ? 2.f : 1.f;
            tv += d * d * w; mn += fmaxf(d, 0.f);
        }
        if (z < 32) {
            const float d = v - g_lut[idx + 1089];
            const float w = (z == 0 || z == 31) ? 2.f : 1.f;
            tv += d * d * w; mn += fmaxf(d, 0.f);
        }
    }
#pragma unroll
    for (int o = 16; o > 0; o >>= 1) {
        tv += __shfl_xor_sync(0xffffffffu, tv, o);
        mn += __shfl_xor_sync(0xffffffffu, mn, o);
    }
    __shared__ float stv[8], smn[8];
    const int lane = threadIdx.x & 31, wp = threadIdx.x >> 5;
    if (lane == 0) { stv[wp] = tv; smn[wp] = mn; }
    __syncthreads();
    if (threadIdx.x == 0) {
        float a = 0.f, m = 0.f;
#pragma unroll
        for (int i = 0; i < 8; ++i) { a += stv[i]; m += smn[i]; }
        atomicAdd(&g_acc[0], a);
        atomicAdd(&g_acc[1], m);
    }
}

// ---------------------------------------------------------------------------
// K6: softmax routing + trilinear LUT blend + weights_norm  (1 thread/pixel)
// ---------------------------------------------------------------------------
__global__ void k_final(const float* __restrict__ img, float* __restrict__ out) {
    const int pix = blockIdx.x * 256 + threadIdx.x;  // exactly NPIXC threads
    const int b = pix >> 16;
    const int p = pix & 0xFFFF;

    const float rn = img[(size_t)(b * 3 + 0) * HWC + p] * 0.5f + 0.5f;
    const float gn = img[(size_t)(b * 3 + 1) * HWC + p] * 0.5f + 0.5f;
    const float bn = img[(size_t)(b * 3 + 2) * HWC + p] * 0.5f + 0.5f;
    const float cx = fminf(fmaxf(rn * 32.f, 0.f), 32.f);
    const float cy = fminf(fmaxf(gn * 32.f, 0.f), 32.f);
    const float cz = fminf(fmaxf(bn * 32.f, 0.f), 32.f);
    const int x0 = min((int)cx, 31);
    const int y0 = min((int)cy, 31);
    const int z0 = min((int)cz, 31);
    const float xd = cx - (float)x0, yd = cy - (float)y0, zd = cz - (float)z0;

    float rv[5];
    const float* rf = g_rt2 + (size_t)(b * KK) * HWC + p;
    float m = -1e30f;
#pragma unroll
    for (int k = 0; k < KK; ++k) { rv[k] = rf[(size_t)k * HWC]; m = fmaxf(m, rv[k]); }
    float se = 0.f;
#pragma unroll
    for (int k = 0; k < KK; ++k) { rv[k] = expf(rv[k] - m); se += rv[k]; }
    const float inv = 1.f / se;

    const int o000 = z0 * D2C + y0 * 33 + x0;
    float a0 = 0.f, a1 = 0.f, a2 = 0.f, wn = 0.f;
#pragma unroll
    for (int k = 0; k < KK; ++k) {
        const float pw = rv[k] * inv;
        wn += pw * pw;
        const float* L = g_lut + (size_t)(b * KK + k) * LUTBK + o000;
#pragma unroll
        for (int ch = 0; ch < 3; ++ch) {
            const float* Lc = L + ch * D3C;
            const float c000 = Lc[0],    c001 = Lc[1];
            const float c010 = Lc[33],   c011 = Lc[34];
            const float c100 = Lc[1089], c101 = Lc[1090];
            const float c110 = Lc[1122], c111 = Lc[1123];
            const float c00 = c000 + (c001 - c000) * xd;
            const float c01 = c010 + (c011 - c010) * xd;
            const float c10 = c100 + (c101 - c100) * xd;
            const float c11 = c110 + (c111 - c110) * xd;
            const float c0 = c00 + (c01 - c00) * yd;
            const float c1 = c10 + (c11 - c10) * yd;
            const float val = c0 + (c1 - c0) * zd;
            if (ch == 0) a0 += val * pw;
            else if (ch == 1) a1 += val * pw;
            else a2 += val * pw;
        }
    }
    out[OUT_LUT_OFF + (size_t)(b * 3 + 0) * HWC + p] = a0;
    out[OUT_LUT_OFF + (size_t)(b * 3 + 1) * HWC + p] = a1;
    out[OUT_LUT_OFF + (size_t)(b * 3 + 2) * HWC + p] = a2;

#pragma unroll
    for (int o = 16; o > 0; o >>= 1) wn += __shfl_xor_sync(0xffffffffu, wn, o);
    __shared__ float swn[8];
    const int lane = threadIdx.x & 31, wp = threadIdx.x >> 5;
    if (lane == 0) swn[wp] = wn;
    __syncthreads();
    if (threadIdx.x == 0) {
        float s = 0.f;
#pragma unroll
        for (int i = 0; i < 8; ++i) s += swn[i];
        atomicAdd(&g_acc[2], s);
    }
}

// ---------------------------------------------------------------------------
// K7: combine regularizers into reg_loss
// ---------------------------------------------------------------------------
__global__ void k_loss(float* __restrict__ out) {
    const float tv = g_acc[0] * (1.f / 104544.f);   // 3*33*33*32
    const float mn = g_acc[1] * (1.f / 104544.f);
    const float wn = g_acc[2] * (1.f / 1310720.f);  // 4*5*256*256
    out[OUT_LOSS_OFF] = 0.0005f * (wn + tv * 0.25f) + 10.f * (mn * 0.25f);
}

// ---------------------------------------------------------------------------
extern "C" void kernel_launch(void* const* d_in, const int* in_sizes, int n_in,
                              void* d_out, int out_size) {
    const float* feat = (const float*)d_in[0];
    const float* img  = (const float*)d_in[1];
    const float* cw   = (const float*)d_in[2];
    const float* cb   = (const float*)d_in[3];
    const float* w1   = (const float*)d_in[4];
    const float* b1   = (const float*)d_in[5];
    const float* w2   = (const float*)d_in[6];
    const float* b2   = (const float*)d_in[7];
    const float* rw0  = (const float*)d_in[8];
    const float* rb0  = (const float*)d_in[9];
    const float* rw1  = (const float*)d_in[10];
    const float* rb1  = (const float*)d_in[11];
    const float* rwt0 = (const float*)d_in[12];
    const float* rbt0 = (const float*)d_in[13];
    const float* rw2  = (const float*)d_in[14];
    const float* rb2  = (const float*)d_in[15];
    const float* rwt1 = (const float*)d_in[16];
    const float* rbt1 = (const float*)d_in[17];
    const float* rw3  = (const float*)d_in[18];
    const float* rb3  = (const float*)d_in[19];
    const float* rwt2 = (const float*)d_in[20];
    const float* rbt2 = (const float*)d_in[21];
    float* out = (float*)d_out;

    k_init     <<<80, 256>>>(out);
    k_im2col   <<<11520, 256>>>(feat);
    k_wt       <<<2880, 256>>>(w1);
    k_lbmma    <<<128, 256>>>(b1);
    k_noise    <<<dim3(16, 8), 256>>>(feat, cw, cb, out);
    k_route0   <<<dim3(32, 4), 128>>>(feat, rw0, rb0);
    k_conv3_32 <<<80, 256>>>(rw1, rb1);
    k_convt_32 <<<320, 256>>>(rwt0, rbt0);
    k_conv3_64 <<<320, 256>>>(rw2, rb2);
    k_convt_64 <<<1280, 256>>>(rwt1, rbt1);
    k_conv3_128<<<1280, 256>>>(rw3, rb3);
    k_convt_128<<<5120, 256>>>(rwt2, rbt2);
    k_gemm     <<<527, 256>>>(w2, b2);
    k_reg      <<<8423, 256>>>();
    k_final    <<<1024, 256>>>(img, out);
    k_loss     <<<1, 1>>>(out);
}